// round 16
// baseline (speedup 1.0000x reference)
#include <cuda_runtime.h>

#define NN 1024
#define NB 32
#define NSTRIPS 128                 // 127 strips of 8 rows + 1 strip of 6 (1022 rows)
#define NUNITS (NB * NSTRIPS)       // 4096 work units
#define GRID 592                    // 148 SMs * 4 blocks, one balanced residency
#define C1 0.122f                   // 2h
#define C2 2.2153277e-12f           // 16 h^4 * 1e-8

__device__ double g_acc[2];         // [0]=sum(zc*cr), [1]=sum(zc)
__device__ unsigned int g_done;

__device__ __forceinline__ float sqrt_approx(float x) {
    float y; asm("sqrt.approx.f32 %0, %1;" : "=f"(y) : "f"(x)); return y;
}
__device__ __forceinline__ float rcp_approx(float x) {
    float y; asm("rcp.approx.f32 %0, %1;" : "=f"(y) : "f"(x)); return y;
}

struct Row { float lf; float4 v; float rt; };

// Load 6 values: clamped left halo, aligned float4, clamped right halo.
// Clamped halos only feed boundary-masked pixels, so garbage there is safe.
__device__ __forceinline__ void load_row(const float* __restrict__ rb, int x0,
                                         int cLF, int cRT, Row& r) {
    r.v  = *reinterpret_cast<const float4*>(rb + x0);
    r.lf = rb[cLF];
    r.rt = rb[cRT];
}

// Scalar epilogue for one pixel: curvature-relu + sign-xor zero-crossing.
__device__ __forceinline__ void px_tail(float num, float d,
                                        float c, float e, float w,
                                        float n, float s, bool valid,
                                        float& ln, float& lc) {
    float sd   = sqrt_approx(d);
    float den  = fmaf(C1 * sd, d, C2);       // 2h*d^1.5 + 16h^4*eps (exact rescale)
    float curv = num * rcp_approx(den);
    float cr   = fmaf(curv, curv, -1.0f);
    cr = fmaxf(cr, 0.0f);

    int ci = __float_as_int(c);
    int x1 = (ci ^ __float_as_int(e)) | (ci ^ __float_as_int(w));
    int x2 = (ci ^ __float_as_int(s)) | (ci ^ __float_as_int(n));
    bool ok = ((x1 | x2) < 0) && valid;
    if (ok) { ln += cr; lc += 1.0f; }
}

__device__ __forceinline__ void row_compute(const Row& t, const Row& m,
                                            const Row& bo,
                                            bool v0, bool v3,
                                            float& ln, float& lc) {
    float dv0 = bo.v.x - t.v.x;
    float dv1 = bo.v.y - t.v.y;
    float dv2 = bo.v.z - t.v.z;
    float dv3 = bo.v.w - t.v.w;
    float dvL = bo.lf  - t.lf;
    float dvR = bo.rt  - t.rt;

    // pixel 0 (center X0)
    {
        float a   = m.v.y - m.lf;
        float dxy = dv1 - dvL;
        float tt  = a - dv0;
        float num = dxy * (tt * tt);
        float d   = fmaf(a, a, dv0 * dv0);
        px_tail(num, d, m.v.x, m.v.y, m.lf, t.v.x, bo.v.x, v0, ln, lc);
    }
    // pixel 1 (center X1)
    {
        float a   = m.v.z - m.v.x;
        float dxy = dv2 - dv0;
        float tt  = a - dv1;
        float num = dxy * (tt * tt);
        float d   = fmaf(a, a, dv1 * dv1);
        px_tail(num, d, m.v.y, m.v.z, m.v.x, t.v.y, bo.v.y, true, ln, lc);
    }
    // pixel 2 (center X2)
    {
        float a   = m.v.w - m.v.y;
        float dxy = dv3 - dv1;
        float tt  = a - dv2;
        float num = dxy * (tt * tt);
        float d   = fmaf(a, a, dv2 * dv2);
        px_tail(num, d, m.v.z, m.v.w, m.v.y, t.v.z, bo.v.z, true, ln, lc);
    }
    // pixel 3 (center X3)
    {
        float a   = m.rt - m.v.z;
        float dxy = dvR - dv2;
        float tt  = a - dv3;
        float num = dxy * (tt * tt);
        float d   = fmaf(a, a, dv3 * dv3);
        px_tail(num, d, m.v.w, m.rt, m.v.z, t.v.w, bo.v.w, v3, ln, lc);
    }
}

// Software-pipelined strip: 4-slot row buffer, loads issued one full
// row_compute ahead of first use (load row r+3, compute row r).
template <int R>
__device__ __forceinline__ void do_strip(const float* __restrict__ rb, int x0,
                                         int cLF, int cRT,
                                         bool v0, bool v3,
                                         float& ln, float& lc) {
    Row buf[4];
    load_row(rb,          x0, cLF, cRT, buf[0]);
    load_row(rb + NN,     x0, cLF, cRT, buf[1]);
    load_row(rb + 2 * NN, x0, cLF, cRT, buf[2]);
    #pragma unroll
    for (int r = 0; r < R; ++r) {
        if (r + 3 < R + 2)
            load_row(rb + (r + 3) * NN, x0, cLF, cRT, buf[(r + 3) & 3]);
        row_compute(buf[r & 3], buf[(r + 1) & 3], buf[(r + 2) & 3],
                    v0, v3, ln, lc);
    }
}

__global__ void __launch_bounds__(256, 4) curv_kernel(const float* __restrict__ phi,
                                                      float* __restrict__ out) {
    const int lane  = threadIdx.x;
    const int chunk = threadIdx.y;              // warp id 0..7
    const int g     = chunk * 32 + lane;        // x-group: columns 4g..4g+3
    const int x0    = 4 * g;

    const int  cLF = (g == 0)   ? 0    : x0 - 1;   // clamped halo indices
    const int  cRT = (g == 255) ? 1023 : x0 + 4;
    const bool v0  = (g != 0);
    const bool v3  = (g != 255);

    float ln = 0.0f;
    float lc = 0.0f;                            // count on fma pipe, exact (< 2^24)

    for (int u = blockIdx.x; u < NUNITS; u += GRID) {
        const int b = u >> 7;           // batch 0..31
        const int s = u & 127;          // strip 0..127
        const float* rb = phi + (size_t)b * NN * NN + (size_t)(s * 8) * NN;
        if (s < 127)
            do_strip<8>(rb, x0, cLF, cRT, v0, v3, ln, lc);
        else
            do_strip<6>(rb, x0, cLF, cRT, v0, v3, ln, lc);
    }

    // warp reduction
    #pragma unroll
    for (int o = 16; o > 0; o >>= 1) {
        ln += __shfl_down_sync(0xffffffffu, ln, o);
        lc += __shfl_down_sync(0xffffffffu, lc, o);
    }

    __shared__ float sn[8];
    __shared__ float sc[8];
    if (lane == 0) { sn[chunk] = ln; sc[chunk] = lc; }
    __syncthreads();

    if (lane == 0 && chunk == 0) {
        double an = 0.0, ac = 0.0;
        #pragma unroll
        for (int k = 0; k < 8; ++k) { an += (double)sn[k]; ac += (double)sc[k]; }
        atomicAdd(&g_acc[0], an);
        atomicAdd(&g_acc[1], ac);
        __threadfence();
        unsigned int ticket = atomicAdd(&g_done, 1u);
        if (ticket == GRID - 1) {
            double snum = atomicAdd(&g_acc[0], 0.0);
            double sden = atomicAdd(&g_acc[1], 0.0);
            out[0] = (float)(snum / (sden + 1e-8));
            // reset for graph replay
            atomicExch((unsigned long long*)&g_acc[0], 0ull);
            atomicExch((unsigned long long*)&g_acc[1], 0ull);
            atomicExch(&g_done, 0u);
        }
    }
}

extern "C" void kernel_launch(void* const* d_in, const int* in_sizes, int n_in,
                              void* d_out, int out_size) {
    const float* phi = (const float*)d_in[0];
    float* out = (float*)d_out;

    dim3 block(32, 8, 1);
    dim3 grid(GRID, 1, 1);
    curv_kernel<<<grid, block>>>(phi, out);
}